// round 8
// baseline (speedup 1.0000x reference)
#include <cuda_runtime.h>
#include <cuda_fp16.h>
#include <cstdint>

#define BB 2
#define SSQ 2048
#define DDM 1024
#define HH 16
#define HD 64
#define NBH (BB*HH)

// ---------------------------------------------------------------------------
// Scratch (__device__ globals; allocation-free rule)
// ---------------------------------------------------------------------------
__device__ __align__(256) __half g_xhi[4096*1024], g_xlo[4096*1024];
__device__ __align__(256) __half g_whi[4*1024*1024], g_wlo[4*1024*1024];
__device__ __align__(256) __half g_qhi[NBH*SSQ*HD], g_qlo[NBH*SSQ*HD];
__device__ __align__(256) __half g_khi[NBH*SSQ*HD], g_klo[NBH*SSQ*HD];
__device__ __align__(256) __half g_vthi[NBH*HD*SSQ], g_vtlo[NBH*HD*SSQ];
__device__ __align__(256) __half g_chi[4096*1024], g_clo[4096*1024];

// ---------------------------------------------------------------------------
// helpers
// ---------------------------------------------------------------------------
__device__ __forceinline__ uint32_t smem_u32(const void* p) {
    uint32_t a;
    asm("{ .reg .u64 t; cvta.to.shared.u64 t, %1; cvt.u32.u64 %0, t; }" : "=r"(a) : "l"(p));
    return a;
}
// D += A * B  (m16n8k16, fp16 in, f32 accum)
__device__ __forceinline__ void mma16816(float* c, const uint32_t* a, const uint32_t* b) {
    asm volatile("mma.sync.aligned.m16n8k16.row.col.f32.f16.f16.f32 "
        "{%0,%1,%2,%3},{%4,%5,%6,%7},{%8,%9},{%0,%1,%2,%3};"
        : "+f"(c[0]), "+f"(c[1]), "+f"(c[2]), "+f"(c[3])
        : "r"(a[0]), "r"(a[1]), "r"(a[2]), "r"(a[3]), "r"(b[0]), "r"(b[1]));
}
__device__ __forceinline__ void ldmx4(uint32_t* r, uint32_t a) {
    asm volatile("ldmatrix.sync.aligned.m8n8.x4.shared.b16 {%0,%1,%2,%3},[%4];"
        : "=r"(r[0]), "=r"(r[1]), "=r"(r[2]), "=r"(r[3]) : "r"(a));
}
__device__ __forceinline__ void cp16(uint32_t d, const void* s) {
    asm volatile("cp.async.ca.shared.global [%0],[%1],16;" :: "r"(d), "l"(s));
}
#define CP_COMMIT() asm volatile("cp.async.commit_group;")
#define CP_WAIT1()  asm volatile("cp.async.wait_group 1;")
#define CP_WAIT0()  asm volatile("cp.async.wait_group 0;")

__device__ __forceinline__ void split_f16(float v, __half& h, __half& l) {
    h = __float2half(v);
    l = __float2half(v - __half2float(h));
}
__device__ __forceinline__ uint32_t pack2h(__half a, __half b) {
    uint16_t ua = __half_as_ushort(a), ub = __half_as_ushort(b);
    return (uint32_t)ua | ((uint32_t)ub << 16);
}

// ---------------------------------------------------------------------------
// fp32 -> (hi, lo) fp16 split.  hs variant + 4-weight batched variant.
// ---------------------------------------------------------------------------
__global__ void conv_split_kernel(const float* __restrict__ in,
                                  __half* __restrict__ hi,
                                  __half* __restrict__ lo, int n4) {
    int i = blockIdx.x * blockDim.x + threadIdx.x;
    if (i >= n4) return;
    float4 v = ((const float4*)in)[i];
    __half h0,l0,h1,l1,h2,l2,h3,l3;
    split_f16(v.x,h0,l0); split_f16(v.y,h1,l1);
    split_f16(v.z,h2,l2); split_f16(v.w,h3,l3);
    uint2 ph, pl;
    ph.x = pack2h(h0,h1); ph.y = pack2h(h2,h3);
    pl.x = pack2h(l0,l1); pl.y = pack2h(l2,l3);
    ((uint2*)hi)[i] = ph;
    ((uint2*)lo)[i] = pl;
}
__global__ void conv_w_kernel(const float* __restrict__ w0, const float* __restrict__ w1,
                              const float* __restrict__ w2, const float* __restrict__ w3) {
    const float* srcs[4] = {w0, w1, w2, w3};
    int z = blockIdx.y;
    int i = blockIdx.x * blockDim.x + threadIdx.x;          // < 262144
    float4 v = ((const float4*)srcs[z])[i];
    __half h0,l0,h1,l1,h2,l2,h3,l3;
    split_f16(v.x,h0,l0); split_f16(v.y,h1,l1);
    split_f16(v.z,h2,l2); split_f16(v.w,h3,l3);
    uint2 ph, pl;
    ph.x = pack2h(h0,h1); ph.y = pack2h(h2,h3);
    pl.x = pack2h(l0,l1); pl.y = pack2h(l2,l3);
    ((uint2*)(g_whi + (size_t)z * 1048576))[i] = ph;
    ((uint2*)(g_wlo + (size_t)z * 1048576))[i] = pl;
}

// ---------------------------------------------------------------------------
// Projection GEMM: X[4096,1024] @ W^T + bias, fp16x3 via mma.sync.
// CTA tile 128x128, 8 warps (warp tile 32x64), kb=32, 2-stage cp.async,
// smem 80KB -> 2 CTAs/SM (4 warps/SMSP latency hiding).  (unchanged R7)
// ---------------------------------------------------------------------------
#define PT   (128*40*2)      // 10240 B per tile (stride 40 halves)
#define PSTG (4*PT)          // A_hi, A_lo, B_hi, B_lo = 40960
#define PROJ_SMEM (2*PSTG)   // 81920 B

__global__ __launch_bounds__(256, 2)
void proj_kernel(const __half* __restrict__ xhi, const __half* __restrict__ xlo,
                 const float* __restrict__ bias0, const float* __restrict__ bias1,
                 const float* __restrict__ bias2, float* __restrict__ outf, int mode)
{
    extern __shared__ char smem[];
    uint32_t sb = smem_u32(smem);
    int tid = threadIdx.x, wid = tid >> 5, lane = tid & 31;
    int g = lane >> 2, tg = lane & 3;
    int z = (mode == 0) ? (int)blockIdx.z : 3;
    const __half* whi = g_whi + (size_t)z * 1048576;
    const __half* wlo = g_wlo + (size_t)z * 1048576;
    const float* bias = (mode == 0) ? (z == 0 ? bias0 : (z == 1 ? bias1 : bias2)) : bias0;
    int m0 = blockIdx.y * 128, n0 = blockIdx.x * 128;
    int wm = (wid & 3) * 32, wn = (wid >> 2) * 64;

    auto issue = [&](int st, int k0) {
        uint32_t base = sb + st * PSTG;
        const __half* srcs[4] = {
            xhi + (size_t)m0 * 1024 + k0, xlo + (size_t)m0 * 1024 + k0,
            whi + (size_t)n0 * 1024 + k0, wlo + (size_t)n0 * 1024 + k0 };
        #pragma unroll
        for (int t = 0; t < 4; t++)
            for (int idx = tid; idx < 512; idx += 256) {
                int row = idx >> 2, j = idx & 3;
                cp16(base + t * PT + (row * 40 + j * 8) * 2,
                     srcs[t] + (size_t)row * 1024 + j * 8);
            }
    };

    float c[2][8][4];
    #pragma unroll
    for (int mt = 0; mt < 2; mt++)
        #pragma unroll
        for (int nt = 0; nt < 8; nt++)
            #pragma unroll
            for (int q = 0; q < 4; q++) c[mt][nt][q] = 0.0f;

    issue(0, 0); CP_COMMIT();
    for (int ks = 0; ks < 32; ks++) {
        if (ks + 1 < 32) { issue((ks + 1) & 1, (ks + 1) * 32); CP_COMMIT(); CP_WAIT1(); }
        else CP_WAIT0();
        __syncthreads();
        uint32_t ss = sb + (ks & 1) * PSTG;
        #pragma unroll
        for (int kk = 0; kk < 2; kk++) {
            uint32_t ah[2][4], al[2][4];
            #pragma unroll
            for (int mt = 0; mt < 2; mt++) {
                int row = wm + mt * 16 + (lane & 15), col = kk * 16 + (lane >> 4) * 8;
                ldmx4(ah[mt], ss + (row * 40 + col) * 2);
                ldmx4(al[mt], ss + PT + (row * 40 + col) * 2);
            }
            #pragma unroll
            for (int np = 0; np < 4; np++) {
                uint32_t bh4[4], bl4[4];
                int n = wn + np * 16 + ((lane >> 4) & 1) * 8 + (lane & 7);
                int c2 = kk * 16 + ((lane >> 3) & 1) * 8;
                ldmx4(bh4, ss + 2 * PT + (n * 40 + c2) * 2);
                ldmx4(bl4, ss + 3 * PT + (n * 40 + c2) * 2);
                #pragma unroll
                for (int mt = 0; mt < 2; mt++) {
                    mma16816(c[mt][2*np],   ah[mt], bh4);
                    mma16816(c[mt][2*np],   ah[mt], bl4);
                    mma16816(c[mt][2*np],   al[mt], bh4);
                    mma16816(c[mt][2*np+1], ah[mt], bh4 + 2);
                    mma16816(c[mt][2*np+1], ah[mt], bl4 + 2);
                    mma16816(c[mt][2*np+1], al[mt], bh4 + 2);
                }
            }
        }
        __syncthreads();
    }

    // epilogue
    #pragma unroll
    for (int mt = 0; mt < 2; mt++) {
        #pragma unroll
        for (int half = 0; half < 2; half++) {
            int row = m0 + wm + mt * 16 + g + half * 8;
            int b_ = row >> 11, s_ = row & (SSQ - 1);
            #pragma unroll
            for (int nt = 0; nt < 8; nt++) {
                int col = n0 + wn + nt * 8 + tg * 2;
                float v0 = c[mt][nt][half * 2 + 0] + bias[col];
                float v1 = c[mt][nt][half * 2 + 1] + bias[col + 1];
                if (mode == 1) {
                    float2 o; o.x = v0; o.y = v1;
                    *(float2*)(outf + (size_t)row * 1024 + col) = o;
                } else {
                    int h = col >> 6, d = col & 63;
                    __half h0, l0, h1, l1;
                    split_f16(v0, h0, l0); split_f16(v1, h1, l1);
                    if (z == 2) {           // V transposed [bh][d][s]
                        size_t base = ((size_t)(b_ * HH + h) * HD + d) * SSQ + s_;
                        g_vthi[base] = h0;        g_vtlo[base] = l0;
                        g_vthi[base + SSQ] = h1;  g_vtlo[base + SSQ] = l1;
                    } else {                // Q/K [bh][s][d]
                        size_t base = ((size_t)(b_ * HH + h) * SSQ + s_) * HD + d;
                        __half* dh = (z == 0) ? g_qhi : g_khi;
                        __half* dl = (z == 0) ? g_qlo : g_klo;
                        *(uint32_t*)(dh + base) = pack2h(h0, h1);
                        *(uint32_t*)(dl + base) = pack2h(l0, l1);
                    }
                }
            }
        }
    }
}

// ---------------------------------------------------------------------------
// Attention: CTA = (b,h) x 128-query tile, 512 threads = 16 warps, 32 key
// tiles of 64. Warp = (m-group 0..7, key-half nh 0..1): S for 16 rows x 32
// keys, softmax quarter, P in registers, PARTIAL O over own 32-key half.
// Halves summed via smem at the end (reusing the Q-tile area).
// ---------------------------------------------------------------------------
#define AQ_HI 0
#define AQ_LO 18432
#define AQ_TOT 36864
#define ST_KHI 0
#define ST_KLO 9216
#define ST_VHI 18432
#define ST_VLO 27648
#define ST_REL 36864
#define ST_MASK 71680
#define ST_SZ 71936
#define ATTN_SMEM (AQ_TOT + 2*ST_SZ)    // 180736
// end-of-kernel reduction buffers (reuse Q area, in floats):
#define RED_O_STRIDE 66                  // 16x64 block, stride 66 floats
#define RED_LS 8448                      // 8 blocks * 16*66 = 8448 floats

__global__ __launch_bounds__(512, 1)
void attn_kernel(const float* __restrict__ rel, const float* __restrict__ mask)
{
    extern __shared__ char smem[];
    uint32_t sb = smem_u32(smem);
    int tid = threadIdx.x, wid = tid >> 5, lane = tid & 31;
    int g = lane >> 2, tg = lane & 3;
    int m = wid & 7, nh = wid >> 3;          // m-group, key-half
    int qt = blockIdx.x, bh = blockIdx.y, b_ = bh >> 4, h_ = bh & 15;
    int r0 = m * 16 + g;                      // row within 128-q tile

    auto issue_stage = [&](int st, int kt) {
        uint32_t base = sb + AQ_TOT + st * ST_SZ;
        const __half* kh = g_khi + ((size_t)bh * SSQ + kt * 64) * HD;
        const __half* kl = g_klo + ((size_t)bh * SSQ + kt * 64) * HD;
        if (tid < 512) {
            int row = tid >> 3, j = tid & 7;
            cp16(base + ST_KHI + (row * 72 + j * 8) * 2, kh + (size_t)row * HD + j * 8);
            cp16(base + ST_KLO + (row * 72 + j * 8) * 2, kl + (size_t)row * HD + j * 8);
        }
        const __half* vh = g_vthi + (size_t)bh * HD * SSQ + (size_t)kt * 64;
        const __half* vl = g_vtlo + (size_t)bh * HD * SSQ + (size_t)kt * 64;
        if (tid < 512) {
            int row = tid >> 3, j = tid & 7;
            cp16(base + ST_VHI + (row * 72 + j * 8) * 2, vh + (size_t)row * SSQ + j * 8);
            cp16(base + ST_VLO + (row * 72 + j * 8) * 2, vl + (size_t)row * SSQ + j * 8);
        }
        const float* rl = rel + ((size_t)h_ * SSQ + qt * 128) * SSQ + (size_t)kt * 64;
        for (int idx = tid; idx < 2048; idx += 512) {
            int row = idx >> 4, j = idx & 15;
            cp16(base + ST_REL + row * 272 + j * 16, rl + (size_t)row * SSQ + j * 4);
        }
        if (tid < 16)
            cp16(base + ST_MASK + tid * 16, mask + (size_t)b_ * SSQ + kt * 64 + tid * 4);
    };

    { // Q tile (once)
        const __half* qh = g_qhi + ((size_t)bh * SSQ + qt * 128) * HD;
        const __half* ql = g_qlo + ((size_t)bh * SSQ + qt * 128) * HD;
        for (int idx = tid; idx < 1024; idx += 512) {
            int row = idx >> 3, j = idx & 7;
            cp16(sb + AQ_HI + (row * 72 + j * 8) * 2, qh + (size_t)row * HD + j * 8);
            cp16(sb + AQ_LO + (row * 72 + j * 8) * 2, ql + (size_t)row * HD + j * 8);
        }
    }
    issue_stage(0, 0); CP_COMMIT();

    float oacc[8][4];                         // 16 rows x 64 d, partial (32 keys)
    #pragma unroll
    for (int nt = 0; nt < 8; nt++)
        #pragma unroll
        for (int q = 0; q < 4; q++) oacc[nt][q] = 0.0f;
    float ls0 = 0.0f, ls1 = 0.0f;

    for (int kt = 0; kt < 32; kt++) {
        if (kt + 1 < 32) { issue_stage((kt + 1) & 1, kt + 1); CP_COMMIT(); CP_WAIT1(); }
        else CP_WAIT0();
        __syncthreads();
        uint32_t ss = sb + AQ_TOT + (kt & 1) * ST_SZ;
        char* scb = smem + AQ_TOT + (kt & 1) * ST_SZ;

        // S = Q.K^T (fp16 x3), own 32-key half
        float sacc[4][4];
        #pragma unroll
        for (int nt = 0; nt < 4; nt++)
            #pragma unroll
            for (int q = 0; q < 4; q++) sacc[nt][q] = 0.0f;
        #pragma unroll
        for (int kk = 0; kk < 4; kk++) {
            uint32_t qhf[4], qlf[4];
            int row = m * 16 + (lane & 15), col = kk * 16 + (lane >> 4) * 8;
            ldmx4(qhf, sb + AQ_HI + (row * 72 + col) * 2);
            ldmx4(qlf, sb + AQ_LO + (row * 72 + col) * 2);
            #pragma unroll
            for (int np = 0; np < 2; np++) {
                uint32_t bh4[4], bl4[4];
                int n = nh * 32 + np * 16 + ((lane >> 4) & 1) * 8 + (lane & 7);
                int c2 = kk * 16 + ((lane >> 3) & 1) * 8;
                ldmx4(bh4, ss + ST_KHI + (n * 72 + c2) * 2);
                ldmx4(bl4, ss + ST_KLO + (n * 72 + c2) * 2);
                mma16816(sacc[2*np],   qhf, bh4);
                mma16816(sacc[2*np],   qhf, bl4);
                mma16816(sacc[2*np],   qlf, bh4);
                mma16816(sacc[2*np+1], qhf, bh4 + 2);
                mma16816(sacc[2*np+1], qhf, bl4 + 2);
                mma16816(sacc[2*np+1], qlf, bh4 + 2);
            }
        }

        // softmax (exp shifted by -4; rel/mask from smem) + pack P (single fp16)
        uint32_t ph[4][2];
        #pragma unroll
        for (int nt = 0; nt < 4; nt++) {
            int c = nh * 32 + nt * 8 + tg * 2;
            float2 mv  = *(const float2*)(scb + ST_MASK + c * 4);
            float2 rv0 = *(const float2*)(scb + ST_REL + r0 * 272 + c * 4);
            float2 rv1 = *(const float2*)(scb + ST_REL + (r0 + 8) * 272 + c * 4);
            float p00 = __expf(fmaf(sacc[nt][0], 0.125f, rv0.x + mv.x - 4.0f));
            float p01 = __expf(fmaf(sacc[nt][1], 0.125f, rv0.y + mv.y - 4.0f));
            float p10 = __expf(fmaf(sacc[nt][2], 0.125f, rv1.x + mv.x - 4.0f));
            float p11 = __expf(fmaf(sacc[nt][3], 0.125f, rv1.y + mv.y - 4.0f));
            ls0 += p00 + p01; ls1 += p10 + p11;
            ph[nt][0] = pack2h(__float2half(p00), __float2half(p01));
            ph[nt][1] = pack2h(__float2half(p10), __float2half(p11));
        }

        // O += P.V (partial over own 32 keys); V^T smem [d][s]
        #pragma unroll
        for (int kk = 0; kk < 2; kk++) {
            uint32_t pa[4] = { ph[2*kk][0], ph[2*kk][1], ph[2*kk+1][0], ph[2*kk+1][1] };
            #pragma unroll
            for (int np = 0; np < 4; np++) {
                uint32_t vh4[4], vl4[4];
                int d = np * 16 + ((lane >> 4) & 1) * 8 + (lane & 7);
                int c2 = nh * 32 + kk * 16 + ((lane >> 3) & 1) * 8;
                ldmx4(vh4, ss + ST_VHI + (d * 72 + c2) * 2);
                ldmx4(vl4, ss + ST_VLO + (d * 72 + c2) * 2);
                mma16816(oacc[2*np],   pa, vh4);
                mma16816(oacc[2*np],   pa, vl4);
                mma16816(oacc[2*np+1], pa, vh4 + 2);
                mma16816(oacc[2*np+1], pa, vl4 + 2);
            }
        }
        __syncthreads();
    }

    // ---- cross-half reduction (reuse Q area) ----
    float* redf = (float*)smem;
    // row-sums: reduce over the 4 lanes sharing each row, then stage per half
    ls0 += __shfl_xor_sync(0xffffffffu, ls0, 1);
    ls0 += __shfl_xor_sync(0xffffffffu, ls0, 2);
    ls1 += __shfl_xor_sync(0xffffffffu, ls1, 1);
    ls1 += __shfl_xor_sync(0xffffffffu, ls1, 2);
    if (tg == 0) {
        redf[RED_LS + nh * 128 + r0]     = ls0;
        redf[RED_LS + nh * 128 + r0 + 8] = ls1;
    }
    // nh=1 warps stage their partial O blocks
    if (nh == 1) {
        int base = m * 16 * RED_O_STRIDE;
        #pragma unroll
        for (int nt = 0; nt < 8; nt++) {
            int c = nt * 8 + tg * 2;
            redf[base + g * RED_O_STRIDE + c]           = oacc[nt][0];
            redf[base + g * RED_O_STRIDE + c + 1]       = oacc[nt][1];
            redf[base + (g + 8) * RED_O_STRIDE + c]     = oacc[nt][2];
            redf[base + (g + 8) * RED_O_STRIDE + c + 1] = oacc[nt][3];
        }
    }
    __syncthreads();
    if (nh == 0) {
        float inv0 = 1.0f / (redf[RED_LS + r0] + redf[RED_LS + 128 + r0]);
        float inv1 = 1.0f / (redf[RED_LS + r0 + 8] + redf[RED_LS + 128 + r0 + 8]);
        int base = m * 16 * RED_O_STRIDE;
        size_t cb0 = ((size_t)(b_ * SSQ + qt * 128 + r0)) * DDM + h_ * HD;
        size_t cb1 = cb0 + (size_t)8 * DDM;
        #pragma unroll
        for (int nt = 0; nt < 8; nt++) {
            int d = nt * 8 + tg * 2;
            float o00 = (oacc[nt][0] + redf[base + g * RED_O_STRIDE + d])           * inv0;
            float o01 = (oacc[nt][1] + redf[base + g * RED_O_STRIDE + d + 1])       * inv0;
            float o10 = (oacc[nt][2] + redf[base + (g + 8) * RED_O_STRIDE + d])     * inv1;
            float o11 = (oacc[nt][3] + redf[base + (g + 8) * RED_O_STRIDE + d + 1]) * inv1;
            __half h0, l0, h1, l1;
            split_f16(o00, h0, l0); split_f16(o01, h1, l1);
            *(uint32_t*)(g_chi + cb0 + d) = pack2h(h0, h1);
            *(uint32_t*)(g_clo + cb0 + d) = pack2h(l0, l1);
            split_f16(o10, h0, l0); split_f16(o11, h1, l1);
            *(uint32_t*)(g_chi + cb1 + d) = pack2h(h0, h1);
            *(uint32_t*)(g_clo + cb1 + d) = pack2h(l0, l1);
        }
    }
}

// ---------------------------------------------------------------------------
extern "C" void kernel_launch(void* const* d_in, const int* in_sizes, int n_in,
                              void* d_out, int out_size)
{
    const float* hs  = (const float*)d_in[0];
    const float* msk = (const float*)d_in[1];
    const float* rel = (const float*)d_in[2];
    const float* Wq  = (const float*)d_in[3];
    const float* bq  = (const float*)d_in[4];
    const float* Wk  = (const float*)d_in[5];
    const float* bk  = (const float*)d_in[6];
    const float* Wv  = (const float*)d_in[7];
    const float* bv  = (const float*)d_in[8];
    const float* Wo  = (const float*)d_in[9];
    const float* bo  = (const float*)d_in[10];
    float* out = (float*)d_out;

    void *xhi, *xlo, *chi, *clo;
    cudaGetSymbolAddress(&xhi, g_xhi); cudaGetSymbolAddress(&xlo, g_xlo);
    cudaGetSymbolAddress(&chi, g_chi); cudaGetSymbolAddress(&clo, g_clo);

    cudaFuncSetAttribute(proj_kernel, cudaFuncAttributeMaxDynamicSharedMemorySize, PROJ_SMEM);
    cudaFuncSetAttribute(attn_kernel, cudaFuncAttributeMaxDynamicSharedMemorySize, ATTN_SMEM);

    conv_split_kernel<<<4096, 256>>>(hs, (__half*)xhi, (__half*)xlo, 1048576);
    conv_w_kernel<<<dim3(1024, 4), 256>>>(Wq, Wk, Wv, Wo);

    proj_kernel<<<dim3(8, 32, 3), 256, PROJ_SMEM>>>((const __half*)xhi, (const __half*)xlo,
                                                    bq, bk, bv, nullptr, 0);
    attn_kernel<<<dim3(16, 32), 512, ATTN_SMEM>>>(rel, msk);
    proj_kernel<<<dim3(8, 32, 1), 256, PROJ_SMEM>>>((const __half*)chi, (const __half*)clo,
                                                    bo, bo, bo, out, 1);
}

// round 9
// speedup vs baseline: 1.2817x; 1.2817x over previous
#include <cuda_runtime.h>
#include <cuda_fp16.h>
#include <cstdint>

#define BB 2
#define SSQ 2048
#define DDM 1024
#define HH 16
#define HD 64
#define NBH (BB*HH)

// ---------------------------------------------------------------------------
// Scratch (__device__ globals; allocation-free rule)
// ---------------------------------------------------------------------------
__device__ __align__(256) __half g_xh [4096*1024];
__device__ __align__(256) __half g_whi[4*1024*1024], g_wlo[4*1024*1024];
__device__ __align__(256) __half g_qhi[NBH*SSQ*HD], g_qlo[NBH*SSQ*HD];
__device__ __align__(256) __half g_khi[NBH*SSQ*HD];
__device__ __align__(256) __half g_vthi[NBH*HD*SSQ];
__device__ __align__(256) __half g_chi[4096*1024], g_clo[4096*1024];

// ---------------------------------------------------------------------------
// helpers
// ---------------------------------------------------------------------------
__device__ __forceinline__ uint32_t smem_u32(const void* p) {
    uint32_t a;
    asm("{ .reg .u64 t; cvta.to.shared.u64 t, %1; cvt.u32.u64 %0, t; }" : "=r"(a) : "l"(p));
    return a;
}
// D += A * B  (m16n8k16, fp16 in, f32 accum)
__device__ __forceinline__ void mma16816(float* c, const uint32_t* a, const uint32_t* b) {
    asm volatile("mma.sync.aligned.m16n8k16.row.col.f32.f16.f16.f32 "
        "{%0,%1,%2,%3},{%4,%5,%6,%7},{%8,%9},{%0,%1,%2,%3};"
        : "+f"(c[0]), "+f"(c[1]), "+f"(c[2]), "+f"(c[3])
        : "r"(a[0]), "r"(a[1]), "r"(a[2]), "r"(a[3]), "r"(b[0]), "r"(b[1]));
}
__device__ __forceinline__ void ldmx4(uint32_t* r, uint32_t a) {
    asm volatile("ldmatrix.sync.aligned.m8n8.x4.shared.b16 {%0,%1,%2,%3},[%4];"
        : "=r"(r[0]), "=r"(r[1]), "=r"(r[2]), "=r"(r[3]) : "r"(a));
}
__device__ __forceinline__ void cp16(uint32_t d, const void* s) {
    asm volatile("cp.async.ca.shared.global [%0],[%1],16;" :: "r"(d), "l"(s));
}
#define CP_COMMIT() asm volatile("cp.async.commit_group;")
#define CP_WAIT1()  asm volatile("cp.async.wait_group 1;")
#define CP_WAIT0()  asm volatile("cp.async.wait_group 0;")

__device__ __forceinline__ void split_f16(float v, __half& h, __half& l) {
    h = __float2half(v);
    l = __float2half(v - __half2float(h));
}
__device__ __forceinline__ uint32_t pack2h(__half a, __half b) {
    uint16_t ua = __half_as_ushort(a), ub = __half_as_ushort(b);
    return (uint32_t)ua | ((uint32_t)ub << 16);
}

// ---------------------------------------------------------------------------
// fp32 -> fp16 converters
// ---------------------------------------------------------------------------
__global__ void conv_hi_kernel(const float* __restrict__ in, __half* __restrict__ hi, int n4) {
    int i = blockIdx.x * blockDim.x + threadIdx.x;
    if (i >= n4) return;
    float4 v = ((const float4*)in)[i];
    uint2 ph;
    ph.x = pack2h(__float2half(v.x), __float2half(v.y));
    ph.y = pack2h(__float2half(v.z), __float2half(v.w));
    ((uint2*)hi)[i] = ph;
}
__global__ void conv_w_kernel(const float* __restrict__ w0, const float* __restrict__ w1,
                              const float* __restrict__ w2, const float* __restrict__ w3) {
    const float* srcs[4] = {w0, w1, w2, w3};
    int z = blockIdx.y;
    int i = blockIdx.x * blockDim.x + threadIdx.x;          // < 262144
    float4 v = ((const float4*)srcs[z])[i];
    __half h0,l0,h1,l1,h2,l2,h3,l3;
    split_f16(v.x,h0,l0); split_f16(v.y,h1,l1);
    split_f16(v.z,h2,l2); split_f16(v.w,h3,l3);
    uint2 ph, pl;
    ph.x = pack2h(h0,h1); ph.y = pack2h(h2,h3);
    pl.x = pack2h(l0,l1); pl.y = pack2h(l2,l3);
    ((uint2*)(g_whi + (size_t)z * 1048576))[i] = ph;
    ((uint2*)(g_wlo + (size_t)z * 1048576))[i] = pl;
}

// ---------------------------------------------------------------------------
// Projection GEMM: X[4096,1024] @ W^T + bias via mma.sync.
// mode 0 (QKV): A = X hi only, x2 (ah*bh + ah*bl). Q -> hi/lo, K/V -> hi.
// mode 1 (O):   A = C hi/lo, x3. fp32 output.
// CTA tile 128x128, 8 warps, kb=32, 2-stage cp.async, 2 CTAs/SM.
// ---------------------------------------------------------------------------
#define PT   (128*40*2)      // 10240 B per tile (stride 40 halves)
#define PSTG (4*PT)          // A_hi, A_lo, B_hi, B_lo = 40960
#define PROJ_SMEM (2*PSTG)   // 81920 B

__global__ __launch_bounds__(256, 2)
void proj_kernel(const __half* __restrict__ xhi, const __half* __restrict__ xlo,
                 const float* __restrict__ bias0, const float* __restrict__ bias1,
                 const float* __restrict__ bias2, float* __restrict__ outf, int mode)
{
    extern __shared__ char smem[];
    uint32_t sb = smem_u32(smem);
    int tid = threadIdx.x, wid = tid >> 5, lane = tid & 31;
    int g = lane >> 2, tg = lane & 3;
    int z = (mode == 0) ? (int)blockIdx.z : 3;
    const __half* whi = g_whi + (size_t)z * 1048576;
    const __half* wlo = g_wlo + (size_t)z * 1048576;
    const float* bias = (mode == 0) ? (z == 0 ? bias0 : (z == 1 ? bias1 : bias2)) : bias0;
    int m0 = blockIdx.y * 128, n0 = blockIdx.x * 128;
    int wm = (wid & 3) * 32, wn = (wid >> 2) * 64;
    const bool x3 = (mode == 1);

    auto issue = [&](int st, int k0) {
        uint32_t base = sb + st * PSTG;
        const __half* srcs[4] = {
            xhi + (size_t)m0 * 1024 + k0, xlo + (size_t)m0 * 1024 + k0,
            whi + (size_t)n0 * 1024 + k0, wlo + (size_t)n0 * 1024 + k0 };
        #pragma unroll
        for (int t = 0; t < 4; t++) {
            if (t == 1 && !x3) continue;
            for (int idx = tid; idx < 512; idx += 256) {
                int row = idx >> 2, j = idx & 3;
                cp16(base + t * PT + (row * 40 + j * 8) * 2,
                     srcs[t] + (size_t)row * 1024 + j * 8);
            }
        }
    };

    float c[2][8][4];
    #pragma unroll
    for (int mt = 0; mt < 2; mt++)
        #pragma unroll
        for (int nt = 0; nt < 8; nt++)
            #pragma unroll
            for (int q = 0; q < 4; q++) c[mt][nt][q] = 0.0f;

    issue(0, 0); CP_COMMIT();
    for (int ks = 0; ks < 32; ks++) {
        if (ks + 1 < 32) { issue((ks + 1) & 1, (ks + 1) * 32); CP_COMMIT(); CP_WAIT1(); }
        else CP_WAIT0();
        __syncthreads();
        uint32_t ss = sb + (ks & 1) * PSTG;
        #pragma unroll
        for (int kk = 0; kk < 2; kk++) {
            uint32_t ah[2][4], al[2][4];
            #pragma unroll
            for (int mt = 0; mt < 2; mt++) {
                int row = wm + mt * 16 + (lane & 15), col = kk * 16 + (lane >> 4) * 8;
                ldmx4(ah[mt], ss + (row * 40 + col) * 2);
                if (x3) ldmx4(al[mt], ss + PT + (row * 40 + col) * 2);
            }
            #pragma unroll
            for (int np = 0; np < 4; np++) {
                uint32_t bh4[4], bl4[4];
                int n = wn + np * 16 + ((lane >> 4) & 1) * 8 + (lane & 7);
                int c2 = kk * 16 + ((lane >> 3) & 1) * 8;
                ldmx4(bh4, ss + 2 * PT + (n * 40 + c2) * 2);
                ldmx4(bl4, ss + 3 * PT + (n * 40 + c2) * 2);
                #pragma unroll
                for (int mt = 0; mt < 2; mt++) {
                    mma16816(c[mt][2*np],   ah[mt], bh4);
                    mma16816(c[mt][2*np],   ah[mt], bl4);
                    mma16816(c[mt][2*np+1], ah[mt], bh4 + 2);
                    mma16816(c[mt][2*np+1], ah[mt], bl4 + 2);
                    if (x3) {
                        mma16816(c[mt][2*np],   al[mt], bh4);
                        mma16816(c[mt][2*np+1], al[mt], bh4 + 2);
                    }
                }
            }
        }
        __syncthreads();
    }

    // epilogue
    #pragma unroll
    for (int mt = 0; mt < 2; mt++) {
        #pragma unroll
        for (int half = 0; half < 2; half++) {
            int row = m0 + wm + mt * 16 + g + half * 8;
            int b_ = row >> 11, s_ = row & (SSQ - 1);
            #pragma unroll
            for (int nt = 0; nt < 8; nt++) {
                int col = n0 + wn + nt * 8 + tg * 2;
                float v0 = c[mt][nt][half * 2 + 0] + bias[col];
                float v1 = c[mt][nt][half * 2 + 1] + bias[col + 1];
                if (mode == 1) {
                    float2 o; o.x = v0; o.y = v1;
                    *(float2*)(outf + (size_t)row * 1024 + col) = o;
                } else {
                    int h = col >> 6, d = col & 63;
                    if (z == 2) {           // V transposed [bh][d][s], hi only
                        size_t base = ((size_t)(b_ * HH + h) * HD + d) * SSQ + s_;
                        g_vthi[base]       = __float2half(v0);
                        g_vthi[base + SSQ] = __float2half(v1);
                    } else if (z == 1) {    // K [bh][s][d], hi only
                        size_t base = ((size_t)(b_ * HH + h) * SSQ + s_) * HD + d;
                        *(uint32_t*)(g_khi + base) = pack2h(__float2half(v0), __float2half(v1));
                    } else {                // Q [bh][s][d], hi/lo
                        size_t base = ((size_t)(b_ * HH + h) * SSQ + s_) * HD + d;
                        __half h0, l0, h1, l1;
                        split_f16(v0, h0, l0); split_f16(v1, h1, l1);
                        *(uint32_t*)(g_qhi + base) = pack2h(h0, h1);
                        *(uint32_t*)(g_qlo + base) = pack2h(l0, l1);
                    }
                }
            }
        }
    }
}

// ---------------------------------------------------------------------------
// Attention: CTA = (b,h) x 128-query tile, 256 threads = 8 warps (16 q-rows
// each), 32 key tiles of 64. Q frags hoisted to registers (hi/lo). K hi-only
// (QK x2), V hi-only (PV x1), P single fp16 (shifted exp). rel+mask prefetched
// via cp.async.
// ---------------------------------------------------------------------------
#define AQ_HI 0
#define AQ_LO 18432
#define AQ_TOT 36864
#define ST_KHI 0
#define ST_VHI 9216
#define ST_REL 18432
#define ST_MASK 53248
#define ST_SZ 53504
#define ATTN_SMEM (AQ_TOT + 2*ST_SZ)    // 143872

__global__ __launch_bounds__(256, 1)
void attn_kernel(const float* __restrict__ rel, const float* __restrict__ mask)
{
    extern __shared__ char smem[];
    uint32_t sb = smem_u32(smem);
    int tid = threadIdx.x, wid = tid >> 5, lane = tid & 31;
    int g = lane >> 2, tg = lane & 3;
    int qt = blockIdx.x, bh = blockIdx.y, b_ = bh >> 4, h_ = bh & 15;
    int r0 = wid * 16 + g;

    auto issue_stage = [&](int st, int kt) {
        uint32_t base = sb + AQ_TOT + st * ST_SZ;
        const __half* kh = g_khi + ((size_t)bh * SSQ + kt * 64) * HD;
        for (int idx = tid; idx < 512; idx += 256) {
            int row = idx >> 3, j = idx & 7;
            cp16(base + ST_KHI + (row * 72 + j * 8) * 2, kh + (size_t)row * HD + j * 8);
        }
        const __half* vh = g_vthi + (size_t)bh * HD * SSQ + (size_t)kt * 64;
        for (int idx = tid; idx < 512; idx += 256) {
            int row = idx >> 3, j = idx & 7;
            cp16(base + ST_VHI + (row * 72 + j * 8) * 2, vh + (size_t)row * SSQ + j * 8);
        }
        const float* rl = rel + ((size_t)h_ * SSQ + qt * 128) * SSQ + (size_t)kt * 64;
        for (int idx = tid; idx < 2048; idx += 256) {
            int row = idx >> 4, j = idx & 15;
            cp16(base + ST_REL + row * 272 + j * 16, rl + (size_t)row * SSQ + j * 4);
        }
        if (tid < 16)
            cp16(base + ST_MASK + tid * 16, mask + (size_t)b_ * SSQ + kt * 64 + tid * 4);
    };

    { // Q tile (once)
        const __half* qh = g_qhi + ((size_t)bh * SSQ + qt * 128) * HD;
        const __half* ql = g_qlo + ((size_t)bh * SSQ + qt * 128) * HD;
        for (int idx = tid; idx < 1024; idx += 256) {
            int row = idx >> 3, j = idx & 7;
            cp16(sb + AQ_HI + (row * 72 + j * 8) * 2, qh + (size_t)row * HD + j * 8);
            cp16(sb + AQ_LO + (row * 72 + j * 8) * 2, ql + (size_t)row * HD + j * 8);
        }
    }
    issue_stage(0, 0); CP_COMMIT();

    uint32_t qhf[4][4], qlf[4][4];       // hoisted Q frags (filled at kt==0)
    float oacc[8][4];
    #pragma unroll
    for (int nt = 0; nt < 8; nt++)
        #pragma unroll
        for (int q = 0; q < 4; q++) oacc[nt][q] = 0.0f;
    float ls0 = 0.0f, ls1 = 0.0f;

    for (int kt = 0; kt < 32; kt++) {
        if (kt + 1 < 32) { issue_stage((kt + 1) & 1, kt + 1); CP_COMMIT(); CP_WAIT1(); }
        else CP_WAIT0();
        __syncthreads();
        uint32_t ss = sb + AQ_TOT + (kt & 1) * ST_SZ;
        char* scb = smem + AQ_TOT + (kt & 1) * ST_SZ;

        if (kt == 0) {                   // hoist Q frags once (Q ready w/ stage 0)
            #pragma unroll
            for (int kk = 0; kk < 4; kk++) {
                int row = wid * 16 + (lane & 15), col = kk * 16 + (lane >> 4) * 8;
                ldmx4(qhf[kk], sb + AQ_HI + (row * 72 + col) * 2);
                ldmx4(qlf[kk], sb + AQ_LO + (row * 72 + col) * 2);
            }
        }

        // S = (qh + ql) . kh   (x2)
        float sacc[8][4];
        #pragma unroll
        for (int nt = 0; nt < 8; nt++)
            #pragma unroll
            for (int q = 0; q < 4; q++) sacc[nt][q] = 0.0f;
        #pragma unroll
        for (int kk = 0; kk < 4; kk++) {
            #pragma unroll
            for (int np = 0; np < 4; np++) {
                uint32_t kh4[4];
                int n = np * 16 + ((lane >> 4) & 1) * 8 + (lane & 7);
                int c2 = kk * 16 + ((lane >> 3) & 1) * 8;
                ldmx4(kh4, ss + ST_KHI + (n * 72 + c2) * 2);
                mma16816(sacc[2*np],   qhf[kk], kh4);
                mma16816(sacc[2*np],   qlf[kk], kh4);
                mma16816(sacc[2*np+1], qhf[kk], kh4 + 2);
                mma16816(sacc[2*np+1], qlf[kk], kh4 + 2);
            }
        }

        // softmax (exp shifted by -4; rel/mask from smem) + pack P (single fp16)
        uint32_t ph[8][2];
        #pragma unroll
        for (int nt = 0; nt < 8; nt++) {
            int c = nt * 8 + tg * 2;
            float2 mv  = *(const float2*)(scb + ST_MASK + c * 4);
            float2 rv0 = *(const float2*)(scb + ST_REL + r0 * 272 + c * 4);
            float2 rv1 = *(const float2*)(scb + ST_REL + (r0 + 8) * 272 + c * 4);
            float p00 = __expf(fmaf(sacc[nt][0], 0.125f, rv0.x + mv.x - 4.0f));
            float p01 = __expf(fmaf(sacc[nt][1], 0.125f, rv0.y + mv.y - 4.0f));
            float p10 = __expf(fmaf(sacc[nt][2], 0.125f, rv1.x + mv.x - 4.0f));
            float p11 = __expf(fmaf(sacc[nt][3], 0.125f, rv1.y + mv.y - 4.0f));
            ls0 += p00 + p01; ls1 += p10 + p11;
            ph[nt][0] = pack2h(__float2half(p00), __float2half(p01));
            ph[nt][1] = pack2h(__float2half(p10), __float2half(p11));
        }

        // O += P . V (V hi only); V^T smem [d][s]
        #pragma unroll
        for (int kk = 0; kk < 4; kk++) {
            uint32_t pa[4] = { ph[2*kk][0], ph[2*kk][1], ph[2*kk+1][0], ph[2*kk+1][1] };
            #pragma unroll
            for (int np = 0; np < 4; np++) {
                uint32_t vh4[4];
                int d = np * 16 + ((lane >> 4) & 1) * 8 + (lane & 7);
                int c2 = kk * 16 + ((lane >> 3) & 1) * 8;
                ldmx4(vh4, ss + ST_VHI + (d * 72 + c2) * 2);
                mma16816(oacc[2*np],   pa, vh4);
                mma16816(oacc[2*np+1], pa, vh4 + 2);
            }
        }
        __syncthreads();
    }

    // row-sum reduce across the 4 lanes sharing a row, normalize, write ctx
    ls0 += __shfl_xor_sync(0xffffffffu, ls0, 1);
    ls0 += __shfl_xor_sync(0xffffffffu, ls0, 2);
    ls1 += __shfl_xor_sync(0xffffffffu, ls1, 1);
    ls1 += __shfl_xor_sync(0xffffffffu, ls1, 2);
    float inv0 = 1.0f / ls0, inv1 = 1.0f / ls1;
    size_t cb0 = ((size_t)(b_ * SSQ + qt * 128 + r0)) * DDM + h_ * HD;
    size_t cb1 = cb0 + (size_t)8 * DDM;
    #pragma unroll
    for (int nt = 0; nt < 8; nt++) {
        int d = nt * 8 + tg * 2;
        __half h0, l0, h1, l1;
        split_f16(oacc[nt][0] * inv0, h0, l0); split_f16(oacc[nt][1] * inv0, h1, l1);
        *(uint32_t*)(g_chi + cb0 + d) = pack2h(h0, h1);
        *(uint32_t*)(g_clo + cb0 + d) = pack2h(l0, l1);
        split_f16(oacc[nt][2] * inv1, h0, l0); split_f16(oacc[nt][3] * inv1, h1, l1);
        *(uint32_t*)(g_chi + cb1 + d) = pack2h(h0, h1);
        *(uint32_t*)(g_clo + cb1 + d) = pack2h(l0, l1);
    }
}

// ---------------------------------------------------------------------------
extern "C" void kernel_launch(void* const* d_in, const int* in_sizes, int n_in,
                              void* d_out, int out_size)
{
    const float* hs  = (const float*)d_in[0];
    const float* msk = (const float*)d_in[1];
    const float* rel = (const float*)d_in[2];
    const float* Wq  = (const float*)d_in[3];
    const float* bq  = (const float*)d_in[4];
    const float* Wk  = (const float*)d_in[5];
    const float* bk  = (const float*)d_in[6];
    const float* Wv  = (const float*)d_in[7];
    const float* bv  = (const float*)d_in[8];
    const float* Wo  = (const float*)d_in[9];
    const float* bo  = (const float*)d_in[10];
    float* out = (float*)d_out;

    void *xh, *chi, *clo;
    cudaGetSymbolAddress(&xh, g_xh);
    cudaGetSymbolAddress(&chi, g_chi); cudaGetSymbolAddress(&clo, g_clo);

    cudaFuncSetAttribute(proj_kernel, cudaFuncAttributeMaxDynamicSharedMemorySize, PROJ_SMEM);
    cudaFuncSetAttribute(attn_kernel, cudaFuncAttributeMaxDynamicSharedMemorySize, ATTN_SMEM);

    conv_hi_kernel<<<4096, 256>>>(hs, (__half*)xh, 1048576);
    conv_w_kernel<<<dim3(1024, 4), 256>>>(Wq, Wk, Wv, Wo);

    proj_kernel<<<dim3(8, 32, 3), 256, PROJ_SMEM>>>((const __half*)xh, (const __half*)xh,
                                                    bq, bk, bv, nullptr, 0);
    attn_kernel<<<dim3(16, 32), 256, ATTN_SMEM>>>(rel, msk);
    proj_kernel<<<dim3(8, 32, 1), 256, PROJ_SMEM>>>((const __half*)chi, (const __half*)clo,
                                                    bo, bo, bo, out, 1);
}